// round 15
// baseline (speedup 1.0000x reference)
#include <cuda_runtime.h>
#include <cstdint>

// UltraTinyGRU fused (R14 math), low-barrier pipeline:
//  - SSTEPS=16, XBUFS=3 smem ring, ONE __syncthreads per stage (32 total)
//  - per-warp cp.async wait BEFORE the barrier publishes all groups
//  - dynamic smem (99.8KB) since 3*32*65*16B > 48KB static limit
// Step body identical to R14: packed f32x2 fused input+hidden chains for r/z,
// separate packed hidden dot for n, 3x shfl.xor with per-lane permuted
// h-weights, tanh.approx activations with sigmoid folded as 0.5+0.5*tanh.

#define GT 512
#define ROWS 32
#define THREADS 128
#define SSTEPS 16
#define NSTAGE (GT / SSTEPS)    // 32
#define XBUFS 3
#define ROWQ 65                 // float4 per row slot (64 data + 1 pad)
#define SMEM_BYTES (XBUFS * ROWS * ROWQ * 16)

__device__ __forceinline__ void cp_async16(void* smem_dst, const void* gmem_src) {
    unsigned int s = (unsigned int)__cvta_generic_to_shared(smem_dst);
    asm volatile("cp.async.cg.shared.global [%0], [%1], 16;\n"
                 :: "r"(s), "l"(gmem_src) : "memory");
}
__device__ __forceinline__ void cp_async_commit() {
    asm volatile("cp.async.commit_group;\n" ::: "memory");
}

__device__ __forceinline__ float tanh_fast(float x) {
    float y;
    asm("tanh.approx.f32 %0, %1;" : "=f"(y) : "f"(x));
    return y;
}

// ---- packed fp32x2 helpers ----
__device__ __forceinline__ double pack2(float lo, float hi) {
    double d;
    asm("mov.b64 %0, {%1, %2};" : "=d"(d) : "f"(lo), "f"(hi));
    return d;
}
__device__ __forceinline__ double fma2(double a, double b, double c) {
    double d;
    asm("fma.rn.f32x2 %0, %1, %2, %3;" : "=d"(d) : "d"(a), "d"(b), "d"(c));
    return d;
}
__device__ __forceinline__ float2 unpack2(double d) {
    float2 r;
    asm("mov.b64 {%0, %1}, %2;" : "=f"(r.x), "=f"(r.y) : "d"(d));
    return r;
}
__device__ __forceinline__ void pack_row(float4 v, float scale, double* dst) {
    dst[0] = pack2(v.x * scale, v.y * scale);
    dst[1] = pack2(v.z * scale, v.w * scale);
}

// 8-FFMA2 single chain over a 16-float row (bias-seeded, hoistable off-chain)
__device__ __forceinline__ double pchain16(const double2 q0, const double2 q1,
                                           const double2 q2, const double2 q3,
                                           const double* w, double bias) {
    double a = fma2(q0.x, w[0], bias);
    a = fma2(q0.y, w[1], a);
    a = fma2(q1.x, w[2], a);
    a = fma2(q1.y, w[3], a);
    a = fma2(q2.x, w[4], a);
    a = fma2(q2.y, w[5], a);
    a = fma2(q3.x, w[6], a);
    a = fma2(q3.y, w[7], a);
    return a;
}

__global__ __launch_bounds__(THREADS, 1)
void gru_fused(const float* __restrict__ x,
               const float* __restrict__ w_ih,
               const float* __restrict__ w_hh,
               const float* __restrict__ b_ih,
               const float* __restrict__ b_hh,
               const float* __restrict__ fc_w,
               const float* __restrict__ fc_b,
               float* __restrict__ out) {
    // dynamic: [XBUFS][ROWS][ROWQ] float4; row stride 65*16B=1040B,
    // 260 words ≡ 4 (mod 32) -> quad-broadcast reads conflict-free.
    extern __shared__ float4 sxr[];

    const int tid = threadIdx.x;
    const int b0  = blockIdx.x * ROWS;
    const int row = tid >> 2;
    const int j   = tid & 3;
    const int b   = b0 + row;

    // ---- packed input weights; r/z pre-halved (sigmoid->tanh fold) ----
    const float4* W = (const float4*)w_ih;
    double wrP[8], wzP[8], wnP[8];
#pragma unroll
    for (int q = 0; q < 4; q++) {
        pack_row(__ldg(&W[(j)     * 4 + q]), 0.5f, &wrP[q * 2]);
        pack_row(__ldg(&W[(4 + j) * 4 + q]), 0.5f, &wzP[q * 2]);
        pack_row(__ldg(&W[(8 + j) * 4 + q]), 1.0f, &wnP[q * 2]);
    }

    // ---- hidden-side weights, PERMUTED per lane for bfly ordering ----
    const double whrP01 = pack2(0.5f * __ldg(&w_hh[(j)     * 4 + (j ^ 0)]),
                                0.5f * __ldg(&w_hh[(j)     * 4 + (j ^ 1)]));
    const double whrP23 = pack2(0.5f * __ldg(&w_hh[(j)     * 4 + (j ^ 2)]),
                                0.5f * __ldg(&w_hh[(j)     * 4 + (j ^ 3)]));
    const double whzP01 = pack2(0.5f * __ldg(&w_hh[(4 + j) * 4 + (j ^ 0)]),
                                0.5f * __ldg(&w_hh[(4 + j) * 4 + (j ^ 1)]));
    const double whzP23 = pack2(0.5f * __ldg(&w_hh[(4 + j) * 4 + (j ^ 2)]),
                                0.5f * __ldg(&w_hh[(4 + j) * 4 + (j ^ 3)]));
    const double whnP01 = pack2(0.5f * __ldg(&w_hh[(8 + j) * 4 + (j ^ 0)]),
                                0.5f * __ldg(&w_hh[(8 + j) * 4 + (j ^ 1)]));
    const double whnP23 = pack2(0.5f * __ldg(&w_hh[(8 + j) * 4 + (j ^ 2)]),
                                0.5f * __ldg(&w_hh[(8 + j) * 4 + (j ^ 3)]));

    const float brh  = 0.5f * (__ldg(&b_ih[j])     + __ldg(&b_hh[j]));
    const float bzh  = 0.5f * (__ldg(&b_ih[4 + j]) + __ldg(&b_hh[4 + j]));
    const float bin  = __ldg(&b_ih[8 + j]);
    const double biasR = pack2(brh, 0.0f);
    const double biasZ = pack2(bzh, 0.0f);
    const double biasN = pack2(bin, 0.0f);
    const double bhnP  = pack2(0.5f * __ldg(&b_hh[8 + j]), 0.0f);

    // ---- stage copy: 128 threads move 32 rows x 1024B = 2048 x 16B ----
    const float4* xbase = (const float4*)x;
    auto issue_stage = [&](int s) {
        float4* dst = sxr + (size_t)(s % XBUFS) * ROWS * ROWQ;
#pragma unroll
        for (int it = 0; it < 16; it++) {
            const int c     = tid + it * THREADS;    // 0..2047
            const int crow  = c >> 6;                // 64 float4 per row-stage
            const int chunk = c & 63;
            const float4* src = xbase + ((size_t)(b0 + crow) * GT + s * SSTEPS) * 4 + chunk;
            cp_async16(&dst[crow * ROWQ + chunk], src);
        }
        cp_async_commit();
    };

    issue_stage(0);
    issue_stage(1);

    // hidden state, bfly ordering: v0 = own component, v_m = h_{j^m}
    float v0 = 0.f, v1 = 0.f, v2 = 0.f, v3 = 0.f;

    for (int s = 0; s < NSTAGE; s++) {
        // per-warp drain of the group carrying stage s, THEN one CTA barrier
        // publishes all warps' groups (stage s data came from every warp).
        if (s == NSTAGE - 1) {
            asm volatile("cp.async.wait_group 0;\n" ::: "memory");
        } else {
            asm volatile("cp.async.wait_group 1;\n" ::: "memory");
        }
        __syncthreads();   // the ONLY barrier per stage

        const double2* rx2 =
            (const double2*)(sxr + (size_t)(s % XBUFS) * ROWS * ROWQ + row * ROWQ);
#pragma unroll 8
        for (int u = 0; u < SSTEPS; u++) {
            const double2 q0 = rx2[u * 4 + 0];
            const double2 q1 = rx2[u * 4 + 1];
            const double2 q2 = rx2[u * 4 + 2];
            const double2 q3 = rx2[u * 4 + 3];

            // input-side packed chains (h-independent, hoistable)
            double aR = pchain16(q0, q1, q2, q3, wrP, biasR);
            double aZ = pchain16(q0, q1, q2, q3, wzP, biasZ);
            double aN = pchain16(q0, q1, q2, q3, wnP, biasN);

            const double hp01 = pack2(v0, v1);
            const double hp23 = pack2(v2, v3);

            // r/z: continue the same packed chain with hidden terms
            aR = fma2(hp01, whrP01, aR);
            aR = fma2(hp23, whrP23, aR);
            const float2 uR = unpack2(aR);
            const float arg_r = uR.x + uR.y;

            aZ = fma2(hp01, whzP01, aZ);
            aZ = fma2(hp23, whzP23, aZ);
            const float2 uZ = unpack2(aZ);
            const float arg_z = uZ.x + uZ.y;

            // n: input and hidden parts separate (r multiplies ghn)
            const float2 uN = unpack2(aN);
            const float gn = uN.x + uN.y;
            double nh = fma2(hp01, whnP01, bhnP);
            nh = fma2(hp23, whnP23, nh);
            const float2 uH = unpack2(nh);
            const float ghn_h = uH.x + uH.y;      // 0.5*(h.w_hh_n + b_hh_n)

            const float tr = tanh_fast(arg_r);
            const float tz = tanh_fast(arg_z);

            const float narg = fmaf(tr, ghn_h, gn + ghn_h);
            const float n    = tanh_fast(narg);

            // hn = n + z*(v0-n), z = 0.5 + 0.5*tz
            const float a  = fmaf(tz, 0.5f, 0.5f);
            const float hn = fmaf(a, v0 - n, n);

            v0 = hn;
            v1 = __shfl_xor_sync(0xffffffffu, hn, 1, 4);
            v2 = __shfl_xor_sync(0xffffffffu, hn, 2, 4);
            v3 = __shfl_xor_sync(0xffffffffu, hn, 3, 4);
        }

        // refill buf (s+2)%3: its last readers were in stage s-1, and all
        // warps passed this stage's barrier after that -> WAR safe.
        if (s + 2 < NSTAGE) {
            issue_stage(s + 2);
        }
    }

    if (j == 0) {
        const float fw0 = __ldg(&fc_w[0]), fw1 = __ldg(&fc_w[1]);
        const float fw2 = __ldg(&fc_w[2]), fw3 = __ldg(&fc_w[3]);
        out[b] = (v0 * fw0 + v1 * fw1) + (v2 * fw2 + v3 * fw3) + __ldg(&fc_b[0]);
    }
}

extern "C" void kernel_launch(void* const* d_in, const int* in_sizes, int n_in,
                              void* d_out, int out_size) {
    const float* x    = (const float*)d_in[0];
    const float* w_ih = (const float*)d_in[1];
    const float* w_hh = (const float*)d_in[2];
    const float* b_ih = (const float*)d_in[3];
    const float* b_hh = (const float*)d_in[4];
    const float* fc_w = (const float*)d_in[5];
    const float* fc_b = (const float*)d_in[6];
    float* out = (float*)d_out;

    // opt-in to >48KB dynamic smem (host API, no allocation; idempotent)
    static int smem_set = 0;
    if (!smem_set) {
        cudaFuncSetAttribute(gru_fused,
                             cudaFuncAttributeMaxDynamicSharedMemorySize,
                             SMEM_BYTES);
        smem_set = 1;
    }

    const int B = out_size;          // 4096
    const int blocks = B / ROWS;     // 128

    gru_fused<<<blocks, THREADS, SMEM_BYTES>>>(x, w_ih, w_hh, b_ih, b_hh,
                                               fc_w, fc_b, out);
}